// round 1
// baseline (speedup 1.0000x reference)
#include <cuda_runtime.h>
#include <math.h>
#include <stdint.h>

#define BATCH 16
#define HDIM  768
#define NDIM  2048

// Scratch (allocation-free rule: __device__ globals)
__device__ float g_E[(size_t)BATCH * NDIM * NDIM];          // unnormalized exp(logits), 256 MiB
__device__ float g_Lpart[(size_t)BATCH * 16 * NDIM];        // per-mtile partial row sums
__device__ float g_L[(size_t)BATCH * NDIM];                 // row sums

__device__ __forceinline__ float tf32r(float x) {
    float y;
    asm("cvt.rna.tf32.f32 %0, %1;" : "=f"(y) : "f"(x));
    return y;
}

__device__ __forceinline__ void mma_tf32(float* c, const unsigned* a, const unsigned* b) {
    asm volatile(
        "mma.sync.aligned.m16n8k8.row.col.f32.tf32.tf32.f32 "
        "{%0,%1,%2,%3}, {%4,%5,%6,%7}, {%8,%9}, {%0,%1,%2,%3};\n"
        : "+f"(c[0]), "+f"(c[1]), "+f"(c[2]), "+f"(c[3])
        : "r"(a[0]), "r"(a[1]), "r"(a[2]), "r"(a[3]),
          "r"(b[0]), "r"(b[1]));
}

// ===========================================================================
// GEMM1: S[n][m] = sum_h Q[h][n] * (K[h][m]+PE[h][m]); epilogue exp + partial
// row sums. CTA tile 128(n) x 128(m), K-chunk 32. 8 warps as 4(M) x 2(N),
// warp tile 32x64.
// Smem tiles k-major [32][136]: frag banks = (8*tig + gid) -> conflict-free.
// ===========================================================================
__global__ __launch_bounds__(256, 2)
void gemm1_kernel(const float* __restrict__ Q, const float* __restrict__ K,
                  const float* __restrict__ PE) {
    __shared__ float Qs[32][136];
    __shared__ float Ks[32][136];
    __shared__ float Lred[2][128];

    const int b   = blockIdx.z;
    const int m0  = blockIdx.x * 128;
    const int n0  = blockIdx.y * 128;
    const int tid = threadIdx.x;
    const int lane = tid & 31;
    const int w    = tid >> 5;
    const int wm   = (w >> 1) * 32;     // 0,32,64,96  (n rows)
    const int wn   = (w & 1) * 64;      // 0,64        (m cols)
    const int gid  = lane >> 2;
    const int tig  = lane & 3;

    const float* Qb = Q  + (size_t)b * HDIM * NDIM;
    const float* Kb = K  + (size_t)b * HDIM * NDIM;
    const float* Pb = PE + (size_t)b * HDIM * NDIM;

    float acc[2][8][4];
#pragma unroll
    for (int i = 0; i < 2; i++)
#pragma unroll
        for (int j = 0; j < 8; j++)
#pragma unroll
            for (int r = 0; r < 4; r++) acc[i][j][r] = 0.f;

    const int krow = tid >> 5;   // k = 8*i + krow
    const int c4   = tid & 31;   // 32 float4 per 128-float row

    for (int h0 = 0; h0 < HDIM; h0 += 32) {
        __syncthreads();
#pragma unroll
        for (int i = 0; i < 4; i++) {
            const int k = i * 8 + krow;
            const float4 qv = *(const float4*)(Qb + (size_t)(h0 + k) * NDIM + n0 + c4 * 4);
            const float4 kv = *(const float4*)(Kb + (size_t)(h0 + k) * NDIM + m0 + c4 * 4);
            const float4 pv = *(const float4*)(Pb + (size_t)(h0 + k) * NDIM + m0 + c4 * 4);
            float4 qt = make_float4(tf32r(qv.x), tf32r(qv.y), tf32r(qv.z), tf32r(qv.w));
            float4 kt = make_float4(tf32r(kv.x + pv.x), tf32r(kv.y + pv.y),
                                    tf32r(kv.z + pv.z), tf32r(kv.w + pv.w));
            *(float4*)(&Qs[k][c4 * 4]) = qt;
            *(float4*)(&Ks[k][c4 * 4]) = kt;
        }
        __syncthreads();
#pragma unroll
        for (int kk = 0; kk < 32; kk += 8) {
            unsigned a[2][4], bf[8][2];
#pragma unroll
            for (int mm = 0; mm < 2; mm++) {
                a[mm][0] = __float_as_uint(Qs[kk + tig    ][wm + mm * 16 + gid    ]);
                a[mm][1] = __float_as_uint(Qs[kk + tig    ][wm + mm * 16 + gid + 8]);
                a[mm][2] = __float_as_uint(Qs[kk + tig + 4][wm + mm * 16 + gid    ]);
                a[mm][3] = __float_as_uint(Qs[kk + tig + 4][wm + mm * 16 + gid + 8]);
            }
#pragma unroll
            for (int nn = 0; nn < 8; nn++) {
                bf[nn][0] = __float_as_uint(Ks[kk + tig    ][wn + nn * 8 + gid]);
                bf[nn][1] = __float_as_uint(Ks[kk + tig + 4][wn + nn * 8 + gid]);
            }
#pragma unroll
            for (int mm = 0; mm < 2; mm++)
#pragma unroll
                for (int nn = 0; nn < 8; nn++)
                    mma_tf32(acc[mm][nn], a[mm], bf[nn]);
        }
    }

    // Epilogue: E = exp(S*scale); write E; partial row sums (deterministic).
    const float scale = 0.03608439182435161f;   // 1/sqrt(768)
    float* Eb = g_E + (size_t)b * NDIM * NDIM;
    float rowsum[2][2] = {{0.f, 0.f}, {0.f, 0.f}};
#pragma unroll
    for (int mm = 0; mm < 2; mm++) {
#pragma unroll
        for (int nn = 0; nn < 8; nn++) {
            float e0 = __expf(acc[mm][nn][0] * scale);
            float e1 = __expf(acc[mm][nn][1] * scale);
            float e2 = __expf(acc[mm][nn][2] * scale);
            float e3 = __expf(acc[mm][nn][3] * scale);
            rowsum[mm][0] += e0 + e1;
            rowsum[mm][1] += e2 + e3;
            const int row = n0 + wm + mm * 16 + gid;
            const int col = m0 + wn + nn * 8 + tig * 2;
            *(float2*)(Eb + (size_t)row * NDIM + col)       = make_float2(e0, e1);
            *(float2*)(Eb + (size_t)(row + 8) * NDIM + col) = make_float2(e2, e3);
        }
    }
#pragma unroll
    for (int mm = 0; mm < 2; mm++)
#pragma unroll
        for (int h = 0; h < 2; h++) {
            float rs = rowsum[mm][h];
            rs += __shfl_xor_sync(0xffffffffu, rs, 1);
            rs += __shfl_xor_sync(0xffffffffu, rs, 2);
            if (tig == 0) Lred[w & 1][wm + mm * 16 + h * 8 + gid] = rs;
        }
    __syncthreads();
    if (tid < 128) {
        float s = Lred[0][tid] + Lred[1][tid];
        g_Lpart[((size_t)b * 16 + blockIdx.x) * NDIM + n0 + tid] = s;
    }
}

// ===========================================================================
// Row-sum reduction: L[b][n] = sum_j Lpart[b][j][n]
// ===========================================================================
__global__ void rowsum_reduce_kernel() {
    const int t = blockIdx.x * blockDim.x + threadIdx.x;
    const int b = t >> 11;
    const int n = t & 2047;
    float s = 0.f;
#pragma unroll
    for (int j = 0; j < 16; j++)
        s += g_Lpart[((size_t)b * 16 + j) * NDIM + n];
    g_L[(size_t)b * NDIM + n] = s;
}

// ===========================================================================
// GEMM2: O[h][n] = (sum_m V[h][m] * E[n][m]) / L[n]
// CTA tile 128(h) x 128(n), K(=m)-chunk 32. Smem row-major [128][40]:
// frag banks = (8*gid + tig) -> conflict-free.
// ===========================================================================
__global__ __launch_bounds__(256, 2)
void gemm2_kernel(const float* __restrict__ V, float* __restrict__ out) {
    __shared__ float Vs[128][40];
    __shared__ float Es[128][40];

    const int b   = blockIdx.z;
    const int n0  = blockIdx.x * 128;
    const int h0  = blockIdx.y * 128;
    const int tid = threadIdx.x;
    const int lane = tid & 31;
    const int w    = tid >> 5;
    const int wm   = (w >> 1) * 32;    // h rows
    const int wn   = (w & 1) * 64;     // n cols
    const int gid  = lane >> 2;
    const int tig  = lane & 3;

    const float* Vb = V   + (size_t)b * HDIM * NDIM;
    const float* Eb = g_E + (size_t)b * NDIM * NDIM;

    float acc[2][8][4];
#pragma unroll
    for (int i = 0; i < 2; i++)
#pragma unroll
        for (int j = 0; j < 8; j++)
#pragma unroll
            for (int r = 0; r < 4; r++) acc[i][j][r] = 0.f;

    const int rrow = tid >> 3;   // row = 32*i + rrow
    const int c4   = tid & 7;    // 8 float4 per 32-float row

    for (int m0 = 0; m0 < NDIM; m0 += 32) {
        __syncthreads();
#pragma unroll
        for (int i = 0; i < 4; i++) {
            const int r = i * 32 + rrow;
            const float4 vv = *(const float4*)(Vb + (size_t)(h0 + r) * NDIM + m0 + c4 * 4);
            const float4 ev = *(const float4*)(Eb + (size_t)(n0 + r) * NDIM + m0 + c4 * 4);
            *(float4*)(&Vs[r][c4 * 4]) =
                make_float4(tf32r(vv.x), tf32r(vv.y), tf32r(vv.z), tf32r(vv.w));
            *(float4*)(&Es[r][c4 * 4]) =
                make_float4(tf32r(ev.x), tf32r(ev.y), tf32r(ev.z), tf32r(ev.w));
        }
        __syncthreads();
#pragma unroll
        for (int kk = 0; kk < 32; kk += 8) {
            unsigned a[2][4], bf[8][2];
#pragma unroll
            for (int mm = 0; mm < 2; mm++) {
                a[mm][0] = __float_as_uint(Vs[wm + mm * 16 + gid    ][kk + tig    ]);
                a[mm][1] = __float_as_uint(Vs[wm + mm * 16 + gid + 8][kk + tig    ]);
                a[mm][2] = __float_as_uint(Vs[wm + mm * 16 + gid    ][kk + tig + 4]);
                a[mm][3] = __float_as_uint(Vs[wm + mm * 16 + gid + 8][kk + tig + 4]);
            }
#pragma unroll
            for (int nn = 0; nn < 8; nn++) {
                bf[nn][0] = __float_as_uint(Es[wn + nn * 8 + gid][kk + tig    ]);
                bf[nn][1] = __float_as_uint(Es[wn + nn * 8 + gid][kk + tig + 4]);
            }
#pragma unroll
            for (int mm = 0; mm < 2; mm++)
#pragma unroll
                for (int nn = 0; nn < 8; nn++)
                    mma_tf32(acc[mm][nn], a[mm], bf[nn]);
        }
    }

    const float* Lb = g_L + (size_t)b * NDIM;
    float* Ob = out + (size_t)b * HDIM * NDIM;
#pragma unroll
    for (int nn = 0; nn < 8; nn++) {
        const int col = n0 + wn + nn * 8 + tig * 2;
        const float inv0 = 1.0f / Lb[col];
        const float inv1 = 1.0f / Lb[col + 1];
#pragma unroll
        for (int mm = 0; mm < 2; mm++) {
            const int hr = h0 + wm + mm * 16 + gid;
            *(float2*)(Ob + (size_t)hr * NDIM + col) =
                make_float2(acc[mm][nn][0] * inv0, acc[mm][nn][1] * inv1);
            *(float2*)(Ob + (size_t)(hr + 8) * NDIM + col) =
                make_float2(acc[mm][nn][2] * inv0, acc[mm][nn][3] * inv1);
        }
    }
}

// ===========================================================================
extern "C" void kernel_launch(void* const* d_in, const int* in_sizes, int n_in,
                              void* d_out, int out_size) {
    const float* q  = (const float*)d_in[0];
    const float* k  = (const float*)d_in[1];
    const float* v  = (const float*)d_in[2];
    const float* pe = (const float*)d_in[3];
    float* out = (float*)d_out;

    dim3 g1(16, 16, BATCH);              // (m-tile, n-tile, batch)
    gemm1_kernel<<<g1, 256>>>(q, k, pe);

    rowsum_reduce_kernel<<<(BATCH * NDIM) / 256, 256>>>();

    dim3 g2(16, 6, BATCH);               // (n-tile, h-tile, batch)
    gemm2_kernel<<<g2, 256>>>(v, out);
}